// round 16
// baseline (speedup 1.0000x reference)
#include <cuda_runtime.h>
#include <cuda_bf16.h>
#include <math.h>

#define NN 768
#define XD 768
#define HID 300
#define HP 304
#define W1COLS 1536
#define NJB 12             // j blocks (768/64)
#define KSPLIT 2

typedef unsigned long long ull;

// Scratch (device globals -- no allocation allowed)
__device__ float g_gpx[KSPLIT][HP * NN];
__device__ float g_gpy[KSPLIT][HP * NN];
__device__ float g_hxT[HP * NN];   // [h][n], pad rows zeroed by build
__device__ float g_hyT[HP * NN];
__device__ ull   g_adup[HP * NN];  // [h][i] {a,a}, a = hy[perm i][h] + b1[h]
__device__ ull   g_w2dup[HP];      // {w,w}, 0 pad
__device__ float g_Ai[NN];
__device__ float g_Cj[NN];
__device__ float g_t0[NN];
__device__ float g_pm[NJB][NN];
__device__ float g_ps[NJB][NN];

__device__ __forceinline__ ull add_f32x2(ull a, ull b) {
    ull d; asm("add.rn.f32x2 %0, %1, %2;" : "=l"(d) : "l"(a), "l"(b)); return d;
}
__device__ __forceinline__ ull fma_f32x2(ull a, ull b, ull c) {
    ull d; asm("fma.rn.f32x2 %0, %1, %2, %3;" : "=l"(d) : "l"(a), "l"(b), "l"(c)); return d;
}
__device__ __forceinline__ ull dup_f32(float f) {
    ull d; unsigned u = __float_as_uint(f);
    asm("mov.b64 %0, {%1, %2};" : "=l"(d) : "r"(u), "r"(u)); return d;
}
__device__ __forceinline__ float lo_f(ull v) { return __uint_as_float((unsigned)(v & 0xffffffffu)); }
__device__ __forceinline__ float hi_f(ull v) { return __uint_as_float((unsigned)(v >> 32)); }
__device__ __forceinline__ float softplus_f(float z) {
    return fmaxf(z, 0.f) + log1pf(expf(-fabsf(z)));
}
__device__ __forceinline__ void cp16(unsigned s, const void* g) {
    asm volatile("cp.async.ca.shared.global [%0], [%1], 16;" :: "r"(s), "l"(g) : "memory");
}
__device__ __forceinline__ void cp_commit() {
    asm volatile("cp.async.commit_group;" ::: "memory");
}
template<int N> __device__ __forceinline__ void cp_wait() {
    asm volatile("cp.async.wait_group %0;" :: "n"(N) : "memory");
}

// ---------------------------------------------------------------------------
// GEMM split-K=2 (unchanged, proven R15): partial[ks][h][n].
// 64 thr, 64n x 64h tile, 8x8 micro. grid (12, 5, 4): z = which*2 + ks.
// ---------------------------------------------------------------------------
__global__ void __launch_bounds__(64) gemm_split(const float* __restrict__ x,
                                                 const float* __restrict__ y,
                                                 const float* __restrict__ W1) {
    __shared__ float sS[32][68];
    __shared__ float sW[32][68];

    const int which = blockIdx.z >> 1;
    const int ks = blockIdx.z & 1;
    const float* S = which ? y : x;
    const int wofs = which ? XD : 0;
    float* gp = which ? &g_gpy[ks][0] : &g_gpx[ks][0];

    const int n0 = blockIdx.x * 64;
    const int h0 = blockIdx.y * 64;
    const int t  = threadIdx.x;
    const int tx = t & 7;
    const int ty = t >> 3;
    const int kstart = ks * 384;
    const int hrow = h0 + t;
    const bool wok = hrow < HID;
    const float* Srow = &S[(size_t)(n0 + t) * XD + kstart];
    const float* Wrow = &W1[(size_t)(wok ? hrow : 0) * W1COLS + wofs + kstart];

    float4 rs[8], rw[8];
    const float4 z4 = make_float4(0.f, 0.f, 0.f, 0.f);
    #pragma unroll
    for (int g = 0; g < 8; g++) {
        rs[g] = *(const float4*)&Srow[g * 4];
        rw[g] = wok ? *(const float4*)&Wrow[g * 4] : z4;
    }

    ull acc[8][4] = {};

    for (int ci = 0; ci < 12; ci++) {
        __syncthreads();
        #pragma unroll
        for (int g = 0; g < 8; g++) {
            sS[g * 4 + 0][t] = rs[g].x; sS[g * 4 + 1][t] = rs[g].y;
            sS[g * 4 + 2][t] = rs[g].z; sS[g * 4 + 3][t] = rs[g].w;
            sW[g * 4 + 0][t] = rw[g].x; sW[g * 4 + 1][t] = rw[g].y;
            sW[g * 4 + 2][t] = rw[g].z; sW[g * 4 + 3][t] = rw[g].w;
        }
        __syncthreads();
        if (ci < 11) {
            const int kb = (ci + 1) * 32;
            #pragma unroll
            for (int g = 0; g < 8; g++) {
                rs[g] = *(const float4*)&Srow[kb + g * 4];
                rw[g] = wok ? *(const float4*)&Wrow[kb + g * 4] : z4;
            }
        }
        #pragma unroll
        for (int kk = 0; kk < 32; kk++) {
            float4 ha = *(const float4*)&sW[kk][ty * 8];
            float4 hb = *(const float4*)&sW[kk][ty * 8 + 4];
            ulonglong2 b01 = *(const ulonglong2*)&sS[kk][tx * 8];
            ulonglong2 b23 = *(const ulonglong2*)&sS[kk][tx * 8 + 4];
            float hv[8] = {ha.x, ha.y, ha.z, ha.w, hb.x, hb.y, hb.z, hb.w};
            ull bp[4] = {b01.x, b01.y, b23.x, b23.y};
            #pragma unroll
            for (int g = 0; g < 8; g++) {
                const ull wd = dup_f32(hv[g]);
                acc[g][0] = fma_f32x2(wd, bp[0], acc[g][0]);
                acc[g][1] = fma_f32x2(wd, bp[1], acc[g][1]);
                acc[g][2] = fma_f32x2(wd, bp[2], acc[g][2]);
                acc[g][3] = fma_f32x2(wd, bp[3], acc[g][3]);
            }
        }
    }

    #pragma unroll
    for (int g = 0; g < 8; g++) {
        const int h = h0 + ty * 8 + g;
        if (h < HID) {
            float4 v0 = make_float4(lo_f(acc[g][0]), hi_f(acc[g][0]),
                                    lo_f(acc[g][1]), hi_f(acc[g][1]));
            float4 v1 = make_float4(lo_f(acc[g][2]), hi_f(acc[g][2]),
                                    lo_f(acc[g][3]), hi_f(acc[g][3]));
            *(float4*)&gp[(size_t)h * NN + n0 + tx * 8]     = v0;
            *(float4*)&gp[(size_t)h * NN + n0 + tx * 8 + 4] = v1;
        }
    }
}

// ---------------------------------------------------------------------------
// build_kernel (fuses old reduce + mid, one launch):
//  blocks 0..303 (h = b): sum split-K partials -> hxT/hyT row h (pads zero),
//    stash hy row in smem, build adup row via SMEM gather (no global re-read).
//  blocks 304..375: stats (t0, Ai, Cj) reading partials directly; blocks
//    304,305 also write w2dup (2*256 = 512 >= HP=304 coverage).
// ---------------------------------------------------------------------------
__global__ void __launch_bounds__(256) build_kernel(const int* __restrict__ perm,
                                                    const float* __restrict__ b1,
                                                    const float* __restrict__ W2,
                                                    const float* __restrict__ b2) {
    __shared__ float srow[NN];        // hy row stash (3KB) / stats red reuse
    const int b = blockIdx.x;
    const int t = threadIdx.x;

    if (b < HP) {
        const int h = b;
        const bool ok = h < HID;
        const float* px0 = &g_gpx[0][(size_t)h * NN];
        const float* px1 = &g_gpx[1][(size_t)h * NN];
        const float* py0 = &g_gpy[0][(size_t)h * NN];
        const float* py1 = &g_gpy[1][(size_t)h * NN];
        #pragma unroll
        for (int e = 0; e < 3; e++) {
            const int i = t + e * 256;
            float vx = 0.f, vy = 0.f;
            if (ok) {
                vx = px0[i] + px1[i];
                vy = py0[i] + py1[i];
            }
            g_hxT[(size_t)h * NN + i] = vx;
            g_hyT[(size_t)h * NN + i] = vy;
            srow[i] = vy;
        }
        __syncthreads();
        const float bh = ok ? b1[h] : 0.f;
        #pragma unroll
        for (int e = 0; e < 3; e++) {
            const int i = t + e * 256;
            float a = ok ? (srow[perm[i]] + bh) : 0.f;
            g_adup[(size_t)h * NN + i] = dup_f32(a);
        }
        return;
    }

    // stats blocks
    const int bs = b - HP;           // 0..71
    const int mode = bs / 24;
    const int tx = t & 31, ty = t >> 5;
    const int n = (bs % 24) * 32 + tx;

    if (bs < 2) {                    // w2dup coverage: 512 threads >= HP
        const int wi = bs * 256 + t;
        if (wi < HP) {
            float w = (wi < HID) ? W2[wi] : 0.f;
            g_w2dup[wi] = dup_f32(w);
        }
    }

    float p = 0.f;
    if (mode == 0) {
        for (int h = ty; h < HID; h += 8) {
            const size_t o = (size_t)h * NN + n;
            float v = g_gpx[0][o] + g_gpx[1][o] + g_gpy[0][o] + g_gpy[1][o] + b1[h];
            p = fmaf(W2[h], fmaxf(v, 0.f), p);
        }
    } else if (mode == 1) {
        const int pi = perm[n];
        for (int h = ty; h < HID; h += 8) {
            const size_t o = (size_t)h * NN + pi;
            p = fmaf(W2[h], g_gpy[0][o] + g_gpy[1][o] + b1[h], p);
        }
    } else {
        for (int h = ty; h < HID; h += 8) {
            const size_t o = (size_t)h * NN + n;
            p = fmaf(W2[h], g_gpx[0][o] + g_gpx[1][o], p);
        }
    }
    // reduce over ty (8 partials per n) via smem (reuse srow: 8*33 <= 768)
    float* red = srow;
    red[ty * 33 + tx] = p;
    __syncthreads();
    if (ty == 0) {
        float s = red[tx];
        #pragma unroll
        for (int k = 1; k < 8; k++) s += red[k * 33 + tx];
        if (mode == 0)      g_t0[n] = softplus_f(s + b2[0]);
        else if (mode == 1) g_Ai[n] = s;
        else                g_Cj[n] = s;
    }
}

// ---------------------------------------------------------------------------
// Pair v8 (unchanged, proven R15: 25.3us): 32i x 64j, 2 h-groups x 128 thr.
// ---------------------------------------------------------------------------
__global__ void __launch_bounds__(256, 2) pair_kernel(const float* __restrict__ b2) {
    __shared__ ull   sA2[2][2][16][32];
    __shared__ float sC[2][2][16][64];
    __shared__ ull   sw2[HP];

    const int g  = threadIdx.y;
    const int t  = threadIdx.x;
    const int tx = t & 15;
    const int ty = t >> 4;
    const int i0 = blockIdx.y * 32;
    const int j0 = blockIdx.x * 64;
    const int row  = t >> 3;
    const int colu = (t & 7) * 4;
    const int colf = (t & 7) * 8;

    for (int h = g * 128 + t; h < HP; h += 256) sw2[h] = g_w2dup[h];

    const int c0 = g ? 10 : 0;
    const int c1 = g ? 19 : 10;

    {
        const int h0 = c0 * 16;
        unsigned da = (unsigned)__cvta_generic_to_shared(&sA2[g][0][row][colu]);
        cp16(da,      &g_adup[(size_t)(h0 + row) * NN + i0 + colu]);
        cp16(da + 16, &g_adup[(size_t)(h0 + row) * NN + i0 + colu + 2]);
        unsigned dc = (unsigned)__cvta_generic_to_shared(&sC[g][0][row][colf]);
        cp16(dc,      &g_hxT[(size_t)(h0 + row) * NN + j0 + colf]);
        cp16(dc + 16, &g_hxT[(size_t)(h0 + row) * NN + j0 + colf + 4]);
        cp_commit();
    }
    __syncthreads();

    ull acc[4][2] = {};

    for (int ch = c0; ch < c1; ch++) {
        const int buf = (ch - c0) & 1;
        if (ch + 1 < c1) {
            const int h1 = (ch + 1) * 16;
            unsigned da = (unsigned)__cvta_generic_to_shared(&sA2[g][buf ^ 1][row][colu]);
            cp16(da,      &g_adup[(size_t)(h1 + row) * NN + i0 + colu]);
            cp16(da + 16, &g_adup[(size_t)(h1 + row) * NN + i0 + colu + 2]);
            unsigned dc = (unsigned)__cvta_generic_to_shared(&sC[g][buf ^ 1][row][colf]);
            cp16(dc,      &g_hxT[(size_t)(h1 + row) * NN + j0 + colf]);
            cp16(dc + 16, &g_hxT[(size_t)(h1 + row) * NN + j0 + colf + 4]);
            cp_commit();
            cp_wait<1>();
        } else {
            cp_wait<0>();
        }
        asm volatile("bar.sync %0, 128;" :: "r"(g + 1) : "memory");

        const int h0 = ch * 16;
        #pragma unroll
        for (int hh = 0; hh < 16; hh++) {
            const ull wv = sw2[h0 + hh];
            ulonglong2 a01 = *(const ulonglong2*)&sA2[g][buf][hh][ty * 4];
            ulonglong2 a23 = *(const ulonglong2*)&sA2[g][buf][hh][ty * 4 + 2];
            ulonglong2 cp  = *(const ulonglong2*)&sC[g][buf][hh][tx * 4];
            ull a2[4] = {a01.x, a01.y, a23.x, a23.y};
            #pragma unroll
            for (int p = 0; p < 4; p++) {
                ull v0 = add_f32x2(a2[p], cp.x) & 0x7FFFFFFF7FFFFFFFULL;
                ull v1 = add_f32x2(a2[p], cp.y) & 0x7FFFFFFF7FFFFFFFULL;
                acc[p][0] = fma_f32x2(wv, v0, acc[p][0]);
                acc[p][1] = fma_f32x2(wv, v1, acc[p][1]);
            }
        }
        asm volatile("bar.sync %0, 128;" :: "r"(g + 1) : "memory");
    }

    ull* cb = (ull*)&sA2[1][0][0][0];
    __syncthreads();
    if (g == 1) {
        #pragma unroll
        for (int p = 0; p < 4; p++) {
            cb[t * 8 + p * 2 + 0] = acc[p][0];
            cb[t * 8 + p * 2 + 1] = acc[p][1];
        }
    }
    __syncthreads();
    if (g == 0) {
        const float bb = b2[0];
        float cj[4], ai[4];
        *(float4*)cj = *(const float4*)&g_Cj[j0 + tx * 4];
        *(float4*)ai = *(const float4*)&g_Ai[i0 + ty * 4];

        #pragma unroll
        for (int p = 0; p < 4; p++) {
            acc[p][0] = add_f32x2(acc[p][0], cb[t * 8 + p * 2 + 0]);
            acc[p][1] = add_f32x2(acc[p][1], cb[t * 8 + p * 2 + 1]);
            float s[4] = {lo_f(acc[p][0]), hi_f(acc[p][0]),
                          lo_f(acc[p][1]), hi_f(acc[p][1])};
            float v[4];
            #pragma unroll
            for (int q = 0; q < 4; q++)
                v[q] = softplus_f(fmaf(0.5f, s[q] + ai[p] + cj[q], bb));

            float m = fmaxf(fmaxf(v[0], v[1]), fmaxf(v[2], v[3]));
            #pragma unroll
            for (int o = 1; o < 16; o <<= 1)
                m = fmaxf(m, __shfl_xor_sync(0xffffffffu, m, o));
            float sm = expf(v[0]-m) + expf(v[1]-m) + expf(v[2]-m) + expf(v[3]-m);
            #pragma unroll
            for (int o = 1; o < 16; o <<= 1)
                sm += __shfl_xor_sync(0xffffffffu, sm, o);
            if (tx == 0) {
                g_pm[blockIdx.x][i0 + ty * 4 + p] = m;
                g_ps[blockIdx.x][i0 + ty * 4 + p] = sm;
            }
        }
    }
}

// ---------------------------------------------------------------------------
// Fused tail (unchanged, proven R15): guarded power-of-two tree.
// ---------------------------------------------------------------------------
__global__ void tail_kernel(float* __restrict__ out) {
    __shared__ float r0[768], r1[768];
    const int t = threadIdx.x;

    float m = -INFINITY;
    #pragma unroll
    for (int jb = 0; jb < NJB; jb++) m = fmaxf(m, g_pm[jb][t]);
    float s = 0.f;
    #pragma unroll
    for (int jb = 0; jb < NJB; jb++) s += g_ps[jb][t] * expf(g_pm[jb][t] - m);
    r1[t] = m + logf(s);
    r0[t] = g_t0[t];
    __syncthreads();

    #pragma unroll
    for (int st = 512; st > 0; st >>= 1) {
        if (t < st && t + st < NN) { r0[t] += r0[t + st]; r1[t] += r1[t + st]; }
        __syncthreads();
    }
    if (t == 0)
        out[0] = r0[0] / (float)NN - (r1[0] / (float)NN - logf((float)NN));
}

// ---------------------------------------------------------------------------
// Inputs: x_samples, y_samples, perm, W1, b1, W2, b2
// ---------------------------------------------------------------------------
extern "C" void kernel_launch(void* const* d_in, const int* in_sizes, int n_in,
                              void* d_out, int out_size) {
    const float* x    = (const float*)d_in[0];
    const float* y    = (const float*)d_in[1];
    const int*   perm = (const int*)d_in[2];
    const float* W1   = (const float*)d_in[3];
    const float* b1   = (const float*)d_in[4];
    const float* W2   = (const float*)d_in[5];
    const float* b2   = (const float*)d_in[6];
    float* out = (float*)d_out;

    gemm_split<<<dim3(NN / 64, 5, 4), 64>>>(x, y, W1);              // idx 0
    build_kernel<<<HP + 72, 256>>>(perm, b1, W2, b2);               // idx 1
    pair_kernel<<<dim3(NN / 64, NN / 32), dim3(128, 2)>>>(b2);      // idx 2
    tail_kernel<<<1, 768>>>(out);                                   // idx 3 (profiled)
}

// round 17
// speedup vs baseline: 1.0537x; 1.0537x over previous
#include <cuda_runtime.h>
#include <cuda_bf16.h>
#include <math.h>

#define NN 768
#define XD 768
#define HID 300
#define HP 304
#define W1COLS 1536
#define NJB 12             // j blocks (768/64)
#define KSPLIT 4

typedef unsigned long long ull;

// Scratch (device globals -- no allocation allowed)
__device__ float g_gpx[KSPLIT][HP * NN];
__device__ float g_gpy[KSPLIT][HP * NN];
__device__ float g_hxT[HP * NN];   // [h][n], pad rows zeroed by reduce
__device__ float g_hyT[HP * NN];
__device__ ull   g_adup[HP * NN];  // [h][i] {a,a}, a = hy[perm i][h] + b1[h]
__device__ ull   g_w2dup[HP];      // {w,w}, 0 pad
__device__ float g_Ai[NN];
__device__ float g_Cj[NN];
__device__ float g_t0[NN];
__device__ float g_ps[NJB][NN];    // per (jblock,row) plain sum-of-exp

__device__ __forceinline__ ull add_f32x2(ull a, ull b) {
    ull d; asm("add.rn.f32x2 %0, %1, %2;" : "=l"(d) : "l"(a), "l"(b)); return d;
}
__device__ __forceinline__ ull fma_f32x2(ull a, ull b, ull c) {
    ull d; asm("fma.rn.f32x2 %0, %1, %2, %3;" : "=l"(d) : "l"(a), "l"(b), "l"(c)); return d;
}
__device__ __forceinline__ ull dup_f32(float f) {
    ull d; unsigned u = __float_as_uint(f);
    asm("mov.b64 %0, {%1, %2};" : "=l"(d) : "r"(u), "r"(u)); return d;
}
__device__ __forceinline__ float lo_f(ull v) { return __uint_as_float((unsigned)(v & 0xffffffffu)); }
__device__ __forceinline__ float hi_f(ull v) { return __uint_as_float((unsigned)(v >> 32)); }
__device__ __forceinline__ float softplus_f(float z) {
    return fmaxf(z, 0.f) + log1pf(expf(-fabsf(z)));
}
__device__ __forceinline__ void cp16(unsigned s, const void* g) {
    asm volatile("cp.async.ca.shared.global [%0], [%1], 16;" :: "r"(s), "l"(g) : "memory");
}
__device__ __forceinline__ void cp_commit() {
    asm volatile("cp.async.commit_group;" ::: "memory");
}
template<int N> __device__ __forceinline__ void cp_wait() {
    asm volatile("cp.async.wait_group %0;" :: "n"(N) : "memory");
}

// ---------------------------------------------------------------------------
// GEMM split-K=4: partial[ks][h][n] = sum_{quarter ks} S[n][k]*W1[h][k+wofs]
// 64 thr, 64n x 64h tile, 8x8 micro. grid (12, 5, 8): z = which*4 + ks.
// ---------------------------------------------------------------------------
__global__ void __launch_bounds__(64) gemm_split(const float* __restrict__ x,
                                                 const float* __restrict__ y,
                                                 const float* __restrict__ W1) {
    __shared__ float sS[32][68];
    __shared__ float sW[32][68];

    const int which = blockIdx.z >> 2;
    const int ks = blockIdx.z & 3;
    const float* S = which ? y : x;
    const int wofs = which ? XD : 0;
    float* gp = which ? &g_gpy[ks][0] : &g_gpx[ks][0];

    const int n0 = blockIdx.x * 64;
    const int h0 = blockIdx.y * 64;
    const int t  = threadIdx.x;
    const int tx = t & 7;
    const int ty = t >> 3;
    const int kstart = ks * 192;     // 768/4
    const int hrow = h0 + t;
    const bool wok = hrow < HID;
    const float* Srow = &S[(size_t)(n0 + t) * XD + kstart];
    const float* Wrow = &W1[(size_t)(wok ? hrow : 0) * W1COLS + wofs + kstart];

    float4 rs[8], rw[8];
    const float4 z4 = make_float4(0.f, 0.f, 0.f, 0.f);
    #pragma unroll
    for (int g = 0; g < 8; g++) {
        rs[g] = *(const float4*)&Srow[g * 4];
        rw[g] = wok ? *(const float4*)&Wrow[g * 4] : z4;
    }

    ull acc[8][4] = {};

    for (int ci = 0; ci < 6; ci++) {     // 192/32
        __syncthreads();
        #pragma unroll
        for (int g = 0; g < 8; g++) {
            sS[g * 4 + 0][t] = rs[g].x; sS[g * 4 + 1][t] = rs[g].y;
            sS[g * 4 + 2][t] = rs[g].z; sS[g * 4 + 3][t] = rs[g].w;
            sW[g * 4 + 0][t] = rw[g].x; sW[g * 4 + 1][t] = rw[g].y;
            sW[g * 4 + 2][t] = rw[g].z; sW[g * 4 + 3][t] = rw[g].w;
        }
        __syncthreads();
        if (ci < 5) {
            const int kb = (ci + 1) * 32;
            #pragma unroll
            for (int g = 0; g < 8; g++) {
                rs[g] = *(const float4*)&Srow[kb + g * 4];
                rw[g] = wok ? *(const float4*)&Wrow[kb + g * 4] : z4;
            }
        }
        #pragma unroll
        for (int kk = 0; kk < 32; kk++) {
            float4 ha = *(const float4*)&sW[kk][ty * 8];
            float4 hb = *(const float4*)&sW[kk][ty * 8 + 4];
            ulonglong2 b01 = *(const ulonglong2*)&sS[kk][tx * 8];
            ulonglong2 b23 = *(const ulonglong2*)&sS[kk][tx * 8 + 4];
            float hv[8] = {ha.x, ha.y, ha.z, ha.w, hb.x, hb.y, hb.z, hb.w};
            ull bp[4] = {b01.x, b01.y, b23.x, b23.y};
            #pragma unroll
            for (int g = 0; g < 8; g++) {
                const ull wd = dup_f32(hv[g]);
                acc[g][0] = fma_f32x2(wd, bp[0], acc[g][0]);
                acc[g][1] = fma_f32x2(wd, bp[1], acc[g][1]);
                acc[g][2] = fma_f32x2(wd, bp[2], acc[g][2]);
                acc[g][3] = fma_f32x2(wd, bp[3], acc[g][3]);
            }
        }
    }

    #pragma unroll
    for (int g = 0; g < 8; g++) {
        const int h = h0 + ty * 8 + g;
        if (h < HID) {
            float4 v0 = make_float4(lo_f(acc[g][0]), hi_f(acc[g][0]),
                                    lo_f(acc[g][1]), hi_f(acc[g][1]));
            float4 v1 = make_float4(lo_f(acc[g][2]), hi_f(acc[g][2]),
                                    lo_f(acc[g][3]), hi_f(acc[g][3]));
            *(float4*)&gp[(size_t)h * NN + n0 + tx * 8]     = v0;
            *(float4*)&gp[(size_t)h * NN + n0 + tx * 8 + 4] = v1;
        }
    }
}

// ---------------------------------------------------------------------------
// reduce: hxT/hyT = partial sums; zero pad rows; w2dup (blocks 0+1 cover HP).
// ---------------------------------------------------------------------------
__global__ void reduce_kernel(const float* __restrict__ W2) {
    const int m = blockIdx.y;
    const int idx4 = blockIdx.x * 256 + threadIdx.x;
    const int h = idx4 / (NN / 4);
    const int i = (idx4 - h * (NN / 4)) * 4;
    float* outT = m ? g_hyT : g_hxT;

    float4 v = make_float4(0.f, 0.f, 0.f, 0.f);
    if (h < HID) {
        #pragma unroll
        for (int ksp = 0; ksp < KSPLIT; ksp++) {
            const float* p = m ? &g_gpy[ksp][0] : &g_gpx[ksp][0];
            float4 a = *(const float4*)&p[(size_t)h * NN + i];
            v.x += a.x; v.y += a.y; v.z += a.z; v.w += a.w;
        }
    }
    *(float4*)&outT[(size_t)h * NN + i] = v;

    if (m == 0 && blockIdx.x < 2) {
        const int wi = blockIdx.x * 256 + threadIdx.x;
        if (wi < HP) {
            float w = (wi < HID) ? W2[wi] : 0.f;
            g_w2dup[wi] = dup_f32(w);
        }
    }
}

// ---------------------------------------------------------------------------
// mid: blocks 0..227 -> g_adup; 228..299 -> stats (t0, Ai, Cj).
// ---------------------------------------------------------------------------
__global__ void mid_kernel(const int* __restrict__ perm,
                           const float* __restrict__ b1,
                           const float* __restrict__ W2,
                           const float* __restrict__ b2) {
    __shared__ float red[8][33];
    const int b = blockIdx.x;
    const int t = threadIdx.x;

    if (b < 228) {
        const int idx4 = b * 256 + t;
        const int h = idx4 / (NN / 4);
        const int i = (idx4 - h * (NN / 4)) * 4;
        float4 v = make_float4(0.f, 0.f, 0.f, 0.f);
        if (h < HID) {
            const int4 pi = *(const int4*)&perm[i];
            const float* row = &g_hyT[(size_t)h * NN];
            const float bh = b1[h];
            v.x = row[pi.x] + bh; v.y = row[pi.y] + bh;
            v.z = row[pi.z] + bh; v.w = row[pi.w] + bh;
        }
        ulonglong2 d0, d1;
        d0.x = dup_f32(v.x); d0.y = dup_f32(v.y);
        d1.x = dup_f32(v.z); d1.y = dup_f32(v.w);
        *(ulonglong2*)&g_adup[(size_t)h * NN + i]     = d0;
        *(ulonglong2*)&g_adup[(size_t)h * NN + i + 2] = d1;
        return;
    }

    const int bs = b - 228;
    const int mode = bs / 24;
    const int tx = t & 31, ty = t >> 5;
    const int n = (bs % 24) * 32 + tx;

    float p = 0.f;
    if (mode == 0) {
        for (int h = ty; h < HID; h += 8) {
            float v = g_hxT[(size_t)h * NN + n] + g_hyT[(size_t)h * NN + n] + b1[h];
            p = fmaf(W2[h], fmaxf(v, 0.f), p);
        }
    } else if (mode == 1) {
        const int pi = perm[n];
        for (int h = ty; h < HID; h += 8)
            p = fmaf(W2[h], g_hyT[(size_t)h * NN + pi] + b1[h], p);
    } else {
        for (int h = ty; h < HID; h += 8)
            p = fmaf(W2[h], g_hxT[(size_t)h * NN + n], p);
    }
    red[ty][tx] = p;
    __syncthreads();
    if (ty == 0) {
        float s = red[0][tx];
        #pragma unroll
        for (int k = 1; k < 8; k++) s += red[k][tx];
        if (mode == 0)      g_t0[n] = softplus_f(s + b2[0]);
        else if (mode == 1) g_Ai[n] = s;
        else                g_Cj[n] = s;
    }
}

// ---------------------------------------------------------------------------
// Pair v9: 32i x 64j, 2 h-groups x 128 thr (R15-proven mainloop).
// Epilogue: plain sum-of-exp partials (softplus outputs bounded -> exp-safe,
// no max stabilization needed).
// ---------------------------------------------------------------------------
__global__ void __launch_bounds__(256, 2) pair_kernel(const float* __restrict__ b2) {
    __shared__ ull   sA2[2][2][16][32];
    __shared__ float sC[2][2][16][64];
    __shared__ ull   sw2[HP];

    const int g  = threadIdx.y;
    const int t  = threadIdx.x;
    const int tx = t & 15;
    const int ty = t >> 4;
    const int i0 = blockIdx.y * 32;
    const int j0 = blockIdx.x * 64;
    const int row  = t >> 3;
    const int colu = (t & 7) * 4;
    const int colf = (t & 7) * 8;

    for (int h = g * 128 + t; h < HP; h += 256) sw2[h] = g_w2dup[h];

    const int c0 = g ? 10 : 0;
    const int c1 = g ? 19 : 10;

    {
        const int h0 = c0 * 16;
        unsigned da = (unsigned)__cvta_generic_to_shared(&sA2[g][0][row][colu]);
        cp16(da,      &g_adup[(size_t)(h0 + row) * NN + i0 + colu]);
        cp16(da + 16, &g_adup[(size_t)(h0 + row) * NN + i0 + colu + 2]);
        unsigned dc = (unsigned)__cvta_generic_to_shared(&sC[g][0][row][colf]);
        cp16(dc,      &g_hxT[(size_t)(h0 + row) * NN + j0 + colf]);
        cp16(dc + 16, &g_hxT[(size_t)(h0 + row) * NN + j0 + colf + 4]);
        cp_commit();
    }
    __syncthreads();

    ull acc[4][2] = {};

    for (int ch = c0; ch < c1; ch++) {
        const int buf = (ch - c0) & 1;
        if (ch + 1 < c1) {
            const int h1 = (ch + 1) * 16;
            unsigned da = (unsigned)__cvta_generic_to_shared(&sA2[g][buf ^ 1][row][colu]);
            cp16(da,      &g_adup[(size_t)(h1 + row) * NN + i0 + colu]);
            cp16(da + 16, &g_adup[(size_t)(h1 + row) * NN + i0 + colu + 2]);
            unsigned dc = (unsigned)__cvta_generic_to_shared(&sC[g][buf ^ 1][row][colf]);
            cp16(dc,      &g_hxT[(size_t)(h1 + row) * NN + j0 + colf]);
            cp16(dc + 16, &g_hxT[(size_t)(h1 + row) * NN + j0 + colf + 4]);
            cp_commit();
            cp_wait<1>();
        } else {
            cp_wait<0>();
        }
        asm volatile("bar.sync %0, 128;" :: "r"(g + 1) : "memory");

        const int h0 = ch * 16;
        #pragma unroll
        for (int hh = 0; hh < 16; hh++) {
            const ull wv = sw2[h0 + hh];
            ulonglong2 a01 = *(const ulonglong2*)&sA2[g][buf][hh][ty * 4];
            ulonglong2 a23 = *(const ulonglong2*)&sA2[g][buf][hh][ty * 4 + 2];
            ulonglong2 cp  = *(const ulonglong2*)&sC[g][buf][hh][tx * 4];
            ull a2[4] = {a01.x, a01.y, a23.x, a23.y};
            #pragma unroll
            for (int p = 0; p < 4; p++) {
                ull v0 = add_f32x2(a2[p], cp.x) & 0x7FFFFFFF7FFFFFFFULL;
                ull v1 = add_f32x2(a2[p], cp.y) & 0x7FFFFFFF7FFFFFFFULL;
                acc[p][0] = fma_f32x2(wv, v0, acc[p][0]);
                acc[p][1] = fma_f32x2(wv, v1, acc[p][1]);
            }
        }
        asm volatile("bar.sync %0, 128;" :: "r"(g + 1) : "memory");
    }

    ull* cb = (ull*)&sA2[1][0][0][0];
    __syncthreads();
    if (g == 1) {
        #pragma unroll
        for (int p = 0; p < 4; p++) {
            cb[t * 8 + p * 2 + 0] = acc[p][0];
            cb[t * 8 + p * 2 + 1] = acc[p][1];
        }
    }
    __syncthreads();
    if (g == 0) {
        const float bb = b2[0];
        float cj[4], ai[4];
        *(float4*)cj = *(const float4*)&g_Cj[j0 + tx * 4];
        *(float4*)ai = *(const float4*)&g_Ai[i0 + ty * 4];

        #pragma unroll
        for (int p = 0; p < 4; p++) {
            acc[p][0] = add_f32x2(acc[p][0], cb[t * 8 + p * 2 + 0]);
            acc[p][1] = add_f32x2(acc[p][1], cb[t * 8 + p * 2 + 1]);
            float s[4] = {lo_f(acc[p][0]), hi_f(acc[p][0]),
                          lo_f(acc[p][1]), hi_f(acc[p][1])};
            // plain sum of exp(softplus(.)) -- bounded, no overflow possible
            float sm = 0.f;
            #pragma unroll
            for (int q = 0; q < 4; q++)
                sm += expf(softplus_f(fmaf(0.5f, s[q] + ai[p] + cj[q], bb)));
            #pragma unroll
            for (int o = 1; o < 16; o <<= 1)
                sm += __shfl_xor_sync(0xffffffffu, sm, o);
            if (tx == 0)
                g_ps[blockIdx.x][i0 + ty * 4 + p] = sm;
        }
    }
}

// ---------------------------------------------------------------------------
// Tail: lse[r] = log(sum_jb ps[jb][r]); reduce t0 & lse means -> scalar.
// Guarded power-of-two tree (768 threads).
// ---------------------------------------------------------------------------
__global__ void tail_kernel(float* __restrict__ out) {
    __shared__ float r0[768], r1[768];
    const int t = threadIdx.x;

    float s = 0.f;
    #pragma unroll
    for (int jb = 0; jb < NJB; jb++) s += g_ps[jb][t];
    r1[t] = logf(s);
    r0[t] = g_t0[t];
    __syncthreads();

    #pragma unroll
    for (int st = 512; st > 0; st >>= 1) {
        if (t < st && t + st < NN) { r0[t] += r0[t + st]; r1[t] += r1[t + st]; }
        __syncthreads();
    }
    if (t == 0)
        out[0] = r0[0] / (float)NN - (r1[0] / (float)NN - logf((float)NN));
}

// ---------------------------------------------------------------------------
// Inputs: x_samples, y_samples, perm, W1, b1, W2, b2
// ---------------------------------------------------------------------------
extern "C" void kernel_launch(void* const* d_in, const int* in_sizes, int n_in,
                              void* d_out, int out_size) {
    const float* x    = (const float*)d_in[0];
    const float* y    = (const float*)d_in[1];
    const int*   perm = (const int*)d_in[2];
    const float* W1   = (const float*)d_in[3];
    const float* b1   = (const float*)d_in[4];
    const float* W2   = (const float*)d_in[5];
    const float* b2   = (const float*)d_in[6];
    float* out = (float*)d_out;

    gemm_split<<<dim3(NN / 64, 5, 8), 64>>>(x, y, W1);              // idx 0
    reduce_kernel<<<dim3(228, 2), 256>>>(W2);                       // idx 1
    mid_kernel<<<300, 256>>>(perm, b1, W2, b2);                     // idx 2
    pair_kernel<<<dim3(NN / 64, NN / 32), dim3(128, 2)>>>(b2);      // idx 3 (profiled)
    tail_kernel<<<1, 768>>>(out);                                   // idx 4
}